// round 12
// baseline (speedup 1.0000x reference)
#include <cuda_runtime.h>
#include <cstdint>

// out[b,i,j,d] = x[b,i,j,d] + W[d, bin] + bias[d],  bin = clip(i-j,-31,31)+31
// B=2, L=512, D=128. x/out: 256 MB each (fp32). Pure HBM stream.
//
// Inputs (metadata order): d_in[0]=x (f32), d_in[1]=idx (i64, unused),
//                          d_in[2]=W (f32 [128,63]), d_in[3]=b (f32 [128])
//
// R11: single kernel; block 0 preps the 32KB table via cp.async.bulk
// (TMA engine path -> bypasses the per-SM L1tex wavefront FIFO that made
// LDG-based prep wait ~2us behind the wave-1 x-load flood). All blocks
// front-batch their 4 x loads, hot-spin on a release flag, then stream.

#define L_DIM   512
#define D_DIM   128
#define NBINS   63
#define TOTAL_F4 (2 * L_DIM * L_DIM * (D_DIM / 4))   // 16,777,216
#define VPT 4
#define TPB 256
#define GRID (TOTAL_F4 / (TPB * VPT))                 // 16384
#define W_ELEMS (D_DIM * NBINS)                       // 8064
#define W_BYTES (W_ELEMS * 4)                         // 32256
#define B_BYTES (D_DIM * 4)                           // 512

// relemb[bin][d] = W[d][bin] + b[d]  (63*128 floats = 32 KB)
__device__ float4 g_relemb[NBINS * (D_DIM / 4)];
__device__ int    g_flag = 0;   // set to NBINS when table ready; reset each run
__device__ int    g_done = 0;   // block-done counter, reset each run

__device__ __forceinline__ int acquire_load(const int* p) {
    int v;
    asm volatile("ld.acquire.gpu.global.b32 %0, [%1];" : "=r"(v) : "l"(p) : "memory");
    return v;
}

__device__ __forceinline__ uint32_t smem_u32(const void* p) {
    return (uint32_t)__cvta_generic_to_shared(p);
}

__global__ __launch_bounds__(TPB)
void add_rel_fused_kernel(const float4* __restrict__ x,
                          float4* __restrict__ out,
                          const float* __restrict__ W,
                          const float* __restrict__ bias) {
    __shared__ __align__(16) float    sW[W_ELEMS];   // 32256 B
    __shared__ __align__(16) float    sB[D_DIM];     // 512 B
    __shared__ __align__(8)  uint64_t s_mbar;

    const int tid  = threadIdx.x;
    const int base = blockIdx.x * (TPB * VPT) + tid;

    // ── Prep (block 0 only): bulk-copy W+bias via the async/TMA path, which
    //    skips the L1tex FIFO, then build the global table from smem. ──
    if (blockIdx.x == 0) {
        uint32_t mb = smem_u32(&s_mbar);
        if (tid == 0) {
            asm volatile("mbarrier.init.shared.b64 [%0], 1;" :: "r"(mb) : "memory");
            asm volatile("fence.proxy.async.shared::cta;" ::: "memory");
            asm volatile("mbarrier.arrive.expect_tx.shared.b64 _, [%0], %1;"
                         :: "r"(mb), "r"((uint32_t)(W_BYTES + B_BYTES)) : "memory");
            asm volatile("cp.async.bulk.shared::cta.global.mbarrier::complete_tx::bytes "
                         "[%0], [%1], %2, [%3];"
                         :: "r"(smem_u32(sW)), "l"(W), "r"((uint32_t)W_BYTES), "r"(mb)
                         : "memory");
            asm volatile("cp.async.bulk.shared::cta.global.mbarrier::complete_tx::bytes "
                         "[%0], [%1], %2, [%3];"
                         :: "r"(smem_u32(sB)), "l"(bias), "r"((uint32_t)B_BYTES), "r"(mb)
                         : "memory");
        }
        __syncthreads();                       // mbar init visible to all waiters
        {                                      // wait for both bulk copies
            uint32_t done;
            do {
                asm volatile(
                    "{\n\t.reg .pred p;\n\t"
                    "mbarrier.try_wait.parity.shared.b64 p, [%1], 0;\n\t"
                    "selp.b32 %0, 1, 0, p;\n\t}"
                    : "=r"(done) : "r"(mb) : "memory");
            } while (!done);
        }
        // table[bin*128 + d] = W[d*63+bin] + bias[d]
        float* tbl = reinterpret_cast<float*>(g_relemb);
        for (int t = tid; t < W_ELEMS; t += TPB) {
            int d  = t / NBINS;
            int bn = t - d * NBINS;
            tbl[bn * D_DIM + d] = sW[t] + sB[d];
        }
        __syncthreads();
        if (tid == 0) {
            __threadfence();                   // release table writes
            atomicAdd(&g_flag, NBINS);
        }
    }

    // ── Front-batch the 4 independent DRAM loads (MLP=4): the 512MB stream
    //    starts immediately; the spin hides under these in-flight loads. ──
    float4 xv[VPT];
    #pragma unroll
    for (int k = 0; k < VPT; k++)
        xv[k] = __ldcs(&x[base + k * TPB]);

    // ── Acquire-spin until the table is published. ──
    if (tid == 0) {
        int v = acquire_load(&g_flag);
        while (v < NBINS) { __nanosleep(32); v = acquire_load(&g_flag); }
    }
    __syncthreads();

    // ── Main stream: bin is warp-uniform; table read is a coalesced L1/L2 hit. ──
    #pragma unroll
    for (int k = 0; k < VPT; k++) {
        int g   = base + k * TPB;
        int d4  = g & 31;
        int row = g >> 5;                         // b*L*L + i*L + j
        int j   = row & (L_DIM - 1);
        int i   = (row >> 9) & (L_DIM - 1);
        int rel = i - j;
        rel = max(-(NBINS / 2), min(NBINS / 2, rel));
        int bin = rel + NBINS / 2;                // 0..62
        float4 rv = g_relemb[bin * 32 + d4];
        float4 ov;
        ov.x = xv[k].x + rv.x;
        ov.y = xv[k].y + rv.y;
        ov.z = xv[k].z + rv.z;
        ov.w = xv[k].w + rv.w;
        __stcs(&out[base + k * TPB], ov);
    }

    // ── Self-reset so every graph replay starts from flag=0/done=0. ──
    __syncthreads();
    if (tid == 0) {
        int d = atomicAdd(&g_done, 1);
        if (d == GRID - 1) {
            g_flag = 0;
            g_done = 0;
            __threadfence();
        }
    }
}

extern "C" void kernel_launch(void* const* d_in, const int* in_sizes, int n_in,
                              void* d_out, int out_size) {
    const float* x    = (const float*)d_in[0];
    const float* W    = (const float*)d_in[2];
    const float* bias = (const float*)d_in[3];
    float* out        = (float*)d_out;

    add_rel_fused_kernel<<<GRID, TPB>>>(
        (const float4*)x, (float4*)out, W, bias);
}

// round 17
// speedup vs baseline: 1.2272x; 1.2272x over previous
#include <cuda_runtime.h>

// out[b,i,j,d] = x[b,i,j,d] + W[d, bin] + bias[d],  bin = clip(i-j,-31,31)+31
// B=2, L=512, D=128. x/out: 256 MB each (fp32). Pure HBM stream.
//
// Inputs (metadata order): d_in[0]=x (f32), d_in[1]=idx (i64, unused),
//                          d_in[2]=W (f32 [128,63]), d_in[3]=b (f32 [128])
//
// R12 (resubmit after infra failure): R5 structure (prep kernel ->
// __device__ table; main kernel PDL-prelaunched under prep). Main kernel:
// __launch_bounds__(256,8) forces regs<=32 (occ ~100%, ~32KB DRAM bytes in
// flight per SM); bin computed warp-uniform from block geometry (fixed i per
// block, j = j0 + warpId + 8k) instead of per-thread row decompose.

#define L_DIM   512
#define D_DIM   128
#define NBINS   63
#define TOTAL_F4 (2 * L_DIM * L_DIM * (D_DIM / 4))   // 16,777,216
#define VPT 4
#define TPB 256

// relemb[bin][d] = W[d][bin] + b[d]  (63*128 floats = 32 KB)
__device__ float4 g_relemb[NBINS * (D_DIM / 4)];

// Coalesced linear read of W (8064 floats), scattered 4B writes into the
// tiny table (lands in L2). 63 blocks for launch-ramp parallelism.
__global__ __launch_bounds__(128)
void build_relemb_kernel(const float* __restrict__ W,
                         const float* __restrict__ bias) {
    int t = blockIdx.x * blockDim.x + threadIdx.x;    // 0 .. 8063
    if (t >= NBINS * D_DIM) return;
    int d   = t / NBINS;                              // W is [128, 63] row-major
    int bin = t - d * NBINS;
    float v = W[t] + bias[d];
    reinterpret_cast<float*>(g_relemb)[bin * D_DIM + d] = v;
}

__global__ __launch_bounds__(TPB, 8)
void add_rel_kernel(const float4* __restrict__ x, float4* __restrict__ out) {
    const int tid    = threadIdx.x;
    const int warpId = tid >> 5;
    const int lane   = tid & 31;
    const int base   = blockIdx.x * (TPB * VPT) + tid;

    // Front-batch the 4 independent DRAM loads (MLP=4). These do NOT depend
    // on the prep kernel, so issue them before the grid-dependency wait.
    float4 xv[VPT];
    #pragma unroll
    for (int k = 0; k < VPT; k++)
        xv[k] = __ldcs(&x[base + k * TPB]);

    // Wait for the prep kernel to complete (PDL); its table writes are
    // visible after this point.
    asm volatile("griddepcontrol.wait;" ::: "memory");

    // Block geometry: 32 consecutive rows, fixed i, j = j0 + warpId + 8k.
    const int row0 = blockIdx.x * ((TPB * VPT) / (D_DIM / 4));  // *32
    const int i    = (row0 >> 9) & (L_DIM - 1);
    const int j0   = row0 & (L_DIM - 1);
    const int c0   = i - j0 - warpId;        // rel at k=0 (warp-uniform)

    #pragma unroll
    for (int k = 0; k < VPT; k++) {
        int rel = c0 - 8 * k;
        rel = max(-(NBINS / 2), min(NBINS / 2, rel));
        const int bin = rel + NBINS / 2;     // 0..62, warp-uniform
        const float4 rv = g_relemb[bin * 32 + lane];   // coalesced L1/L2 hit
        float4 ov;
        ov.x = xv[k].x + rv.x;
        ov.y = xv[k].y + rv.y;
        ov.z = xv[k].z + rv.z;
        ov.w = xv[k].w + rv.w;
        __stcs(&out[base + k * TPB], ov);
    }
}

extern "C" void kernel_launch(void* const* d_in, const int* in_sizes, int n_in,
                              void* d_out, int out_size) {
    const float* x    = (const float*)d_in[0];
    const float* W    = (const float*)d_in[2];
    const float* bias = (const float*)d_in[3];
    float* out        = (float*)d_out;

    build_relemb_kernel<<<NBINS, 128>>>(W, bias);

    // Main kernel with programmatic stream serialization: blocks prelaunch
    // while prep runs; griddepcontrol.wait gates the table reads.
    cudaLaunchConfig_t cfg = {};
    cfg.gridDim  = dim3(TOTAL_F4 / (TPB * VPT));
    cfg.blockDim = dim3(TPB);
    cfg.dynamicSmemBytes = 0;
    cfg.stream = 0;
    cudaLaunchAttribute attrs[1];
    attrs[0].id = cudaLaunchAttributeProgrammaticStreamSerialization;
    attrs[0].val.programmaticStreamSerializationAllowed = 1;
    cfg.attrs = attrs;
    cfg.numAttrs = 1;

    const float4* x4 = (const float4*)x;
    float4* o4       = (float4*)out;
    cudaLaunchKernelEx(&cfg, add_rel_kernel, x4, o4);
}